// round 4
// baseline (speedup 1.0000x reference)
#include <cuda_runtime.h>

#define BN      32768      // total nodes
#define NE      1048576    // total edges
#define NPG     512        // nodes per graph
#define KKEEP   256        // topk keep
#define NGRAPH  64
#define EPSM    1e-7f

// ---------------- scratch (device globals; no allocation allowed) ----------
__device__ float g_h  [BN * 16];
__device__ float g_h1 [BN * 16];
__device__ float g_hp [BN * 16];
__device__ float g_h2 [BN * 32];
__device__ float g_mask[BN];
__device__ int   g_counts[BN];
__device__ int   g_off[BN + 1];
__device__ int   g_cursor[BN];
__device__ int   g_eids[NE];

// ---------------- warp helpers ----------------
__device__ __forceinline__ float wsum(float v) {
    #pragma unroll
    for (int o = 16; o > 0; o >>= 1) v += __shfl_xor_sync(0xffffffffu, v, o);
    return v;
}
__device__ __forceinline__ float wmax(float v) {
    #pragma unroll
    for (int o = 16; o > 0; o >>= 1) v = fmaxf(v, __shfl_xor_sync(0xffffffffu, v, o));
    return v;
}

// ---------------- CSR build ----------------
__global__ void zero_counts_kernel() {
    int i = blockIdx.x * blockDim.x + threadIdx.x;
    if (i < BN) g_counts[i] = 0;
}

__global__ void count_kernel(const int* __restrict__ ei) {
    int e = blockIdx.x * blockDim.x + threadIdx.x;
    if (e < NE) {
        int d = ei[NE + e];
        if ((unsigned)d < BN) atomicAdd(&g_counts[d], 1);
    }
}

__global__ void scan_kernel() {
    __shared__ int wsums[32];
    __shared__ int carry;
    int tid = threadIdx.x, lane = tid & 31, w = tid >> 5;
    if (tid == 0) { carry = 0; g_off[0] = 0; }
    __syncthreads();
    for (int base = 0; base < BN; base += 1024) {
        int v = g_counts[base + tid];
        int x = v;
        #pragma unroll
        for (int o = 1; o < 32; o <<= 1) {
            int y = __shfl_up_sync(0xffffffffu, x, o);
            if (lane >= o) x += y;
        }
        if (lane == 31) wsums[w] = x;
        __syncthreads();
        if (w == 0) {
            int s = wsums[lane];
            int xs = s;
            #pragma unroll
            for (int o = 1; o < 32; o <<= 1) {
                int y = __shfl_up_sync(0xffffffffu, xs, o);
                if (lane >= o) xs += y;
            }
            wsums[lane] = xs;
        }
        __syncthreads();
        int woff = (w == 0) ? 0 : wsums[w - 1];
        int incl = carry + woff + x;
        g_off[base + tid + 1] = incl;
        g_cursor[base + tid]  = incl - v;
        __syncthreads();
        if (tid == 1023) carry = incl;
        __syncthreads();
    }
}

__global__ void scatter_kernel(const int* __restrict__ ei) {
    int e = blockIdx.x * blockDim.x + threadIdx.x;
    if (e < NE) {
        int d = ei[NE + e];
        if ((unsigned)d < BN) {
            int p = atomicAdd(&g_cursor[d], 1);
            if ((unsigned)p < NE) g_eids[p] = e;
        }
    }
}

// ---------------- node encode: h = x @ W_ne + b_ne ----------------
__global__ void encode_kernel(const float* __restrict__ x,
                              const float* __restrict__ Wne,
                              const float* __restrict__ bne) {
    __shared__ float sW[64 * 16];
    __shared__ float sb[16];
    int tx = threadIdx.x;
    for (int i = tx; i < 64 * 16; i += blockDim.x) sW[i] = Wne[i];
    if (tx < 16) sb[tx] = bne[tx];
    __syncthreads();
    int node = blockIdx.x * blockDim.x + tx;
    if (node >= BN) return;
    float acc[16];
    #pragma unroll
    for (int f = 0; f < 16; f++) acc[f] = sb[f];
    const float4* xp = (const float4*)(x + (size_t)node * 64);
    #pragma unroll
    for (int j4 = 0; j4 < 16; j4++) {
        float4 v = __ldg(xp + j4);
        float vv[4] = {v.x, v.y, v.z, v.w};
        #pragma unroll
        for (int k = 0; k < 4; k++) {
            int j = j4 * 4 + k;
            #pragma unroll
            for (int f = 0; f < 16; f++) acc[f] += vv[k] * sW[j * 16 + f];
        }
    }
    float4* op = (float4*)(g_h + (size_t)node * 16);
    op[0] = make_float4(acc[0], acc[1], acc[2], acc[3]);
    op[1] = make_float4(acc[4], acc[5], acc[6], acc[7]);
    op[2] = make_float4(acc[8], acc[9], acc[10], acc[11]);
    op[3] = make_float4(acc[12], acc[13], acc[14], acc[15]);
}

// ---------------- GENConv layer 1 (16 -> 32 -> 16) ----------------
__global__ __launch_bounds__(256)
void conv1_kernel(const int* __restrict__ eidx,
                  const float* __restrict__ eattr,
                  const float* __restrict__ Wee, const float* __restrict__ bee,
                  const float* __restrict__ tptr,
                  const float* __restrict__ W1a, const float* __restrict__ b1a,
                  const float* __restrict__ g1,  const float* __restrict__ be1,
                  const float* __restrict__ W1b, const float* __restrict__ b1b) {
    __shared__ float sWee[256], sbee[16];
    __shared__ float sW1a[512], sb1a[32], sg1[32], sbe1[32];
    __shared__ float sW1b[512], sb1b[16];
    __shared__ float sh_hid[8][33];
    int tx = threadIdx.x;
    for (int i = tx; i < 512; i += 256) { sW1a[i] = W1a[i]; sW1b[i] = W1b[i]; }
    if (tx < 256) sWee[tx] = Wee[tx];
    if (tx < 32) { sb1a[tx] = b1a[tx]; sg1[tx] = g1[tx]; sbe1[tx] = be1[tx]; }
    if (tx < 16) { sbee[tx] = bee[tx]; sb1b[tx] = b1b[tx]; }
    __syncthreads();

    int w = tx >> 5, lane = tx & 31;
    int node = blockIdx.x * 8 + w;
    int start = g_off[node], end = g_off[node + 1];
    if (start < 0) start = 0;
    if (end > NE) end = NE;
    float t = __ldg(tptr);

    float m[16], den[16], num[16];
    #pragma unroll
    for (int f = 0; f < 16; f++) { m[f] = -INFINITY; den[f] = 0.f; num[f] = 0.f; }

    for (int e0 = start; e0 < end; e0 += 32) {
        int idx = e0 + lane;
        bool act = idx < end;
        float msg[16];
        #pragma unroll
        for (int f = 0; f < 16; f++) msg[f] = 0.f;
        if (act) {
            int eid = __ldg(&g_eids[idx]);
            if ((unsigned)eid >= NE) eid = 0;
            int src = __ldg(&eidx[eid]);
            if ((unsigned)src >= BN) src = 0;
            float at[16], hs[16];
            const float4* ap = (const float4*)(eattr) + (size_t)eid * 4;
            float4 v;
            v = __ldg(ap + 0); at[0] = v.x; at[1] = v.y; at[2] = v.z; at[3] = v.w;
            v = __ldg(ap + 1); at[4] = v.x; at[5] = v.y; at[6] = v.z; at[7] = v.w;
            v = __ldg(ap + 2); at[8] = v.x; at[9] = v.y; at[10] = v.z; at[11] = v.w;
            v = __ldg(ap + 3); at[12] = v.x; at[13] = v.y; at[14] = v.z; at[15] = v.w;
            const float4* hp4 = (const float4*)(g_h) + (size_t)src * 4;
            v = hp4[0]; hs[0] = v.x; hs[1] = v.y; hs[2] = v.z; hs[3] = v.w;
            v = hp4[1]; hs[4] = v.x; hs[5] = v.y; hs[6] = v.z; hs[7] = v.w;
            v = hp4[2]; hs[8] = v.x; hs[9] = v.y; hs[10] = v.z; hs[11] = v.w;
            v = hp4[3]; hs[12] = v.x; hs[13] = v.y; hs[14] = v.z; hs[15] = v.w;
            #pragma unroll
            for (int f = 0; f < 16; f++) {
                float acc = sbee[f];
                #pragma unroll
                for (int j = 0; j < 16; j++) acc += at[j] * sWee[j * 16 + f];
                msg[f] = fmaxf(hs[f] + acc, 0.f) + EPSM;
            }
        }
        #pragma unroll
        for (int f = 0; f < 16; f++) {
            float lg = act ? t * msg[f] : -INFINITY;
            float cm = wmax(lg);
            float nm = fmaxf(m[f], cm);
            float ev = act ? __expf(lg - nm) : 0.f;
            float se = wsum(ev);
            float sem = wsum(ev * msg[f]);
            float sc = (nm == -INFINITY) ? 0.f : __expf(m[f] - nm);
            den[f] = den[f] * sc + se;
            num[f] = num[f] * sc + sem;
            m[f] = nm;
        }
    }

    // h1pre = x + aggr
    float pre[16];
    #pragma unroll
    for (int f = 0; f < 16; f++)
        pre[f] = g_h[(size_t)node * 16 + f] + num[f] / fmaxf(den[f], 1e-16f);

    // MLP: 16 -> 32 (LN, relu) -> 16 (then outer relu)
    float acc = sb1a[lane];
    #pragma unroll
    for (int f = 0; f < 16; f++) acc += pre[f] * sW1a[f * 32 + lane];
    float mu = wsum(acc) * (1.f / 32.f);
    float d = acc - mu;
    float var = wsum(d * d) * (1.f / 32.f);
    float y = d * rsqrtf(var + 1e-5f) * sg1[lane] + sbe1[lane];
    y = fmaxf(y, 0.f);
    sh_hid[w][lane] = y;
    __syncwarp();
    if (lane < 16) {
        float o = sb1b[lane];
        #pragma unroll
        for (int l = 0; l < 32; l++) o += sh_hid[w][l] * sW1b[l * 16 + lane];
        g_h1[(size_t)node * 16 + lane] = fmaxf(o, 0.f);
    }
}

// ---------------- TopK pooling (score + mask + hp) ----------------
__global__ void topk_kernel(const float* __restrict__ wpool) {
    __shared__ float s[512];
    __shared__ float swp[16];
    int tid = threadIdx.x;
    if (tid < 16) swp[tid] = wpool[tid];
    __syncthreads();
    float nrm2 = 0.f;
    #pragma unroll
    for (int j = 0; j < 16; j++) nrm2 += swp[j] * swp[j];
    float inv = rsqrtf(nrm2);
    int node = blockIdx.x * NPG + tid;
    const float4* hp4 = (const float4*)(g_h1) + (size_t)node * 4;
    float4 r0 = hp4[0], r1 = hp4[1], r2 = hp4[2], r3 = hp4[3];
    float dot = r0.x * swp[0] + r0.y * swp[1] + r0.z * swp[2] + r0.w * swp[3]
              + r1.x * swp[4] + r1.y * swp[5] + r1.z * swp[6] + r1.w * swp[7]
              + r2.x * swp[8] + r2.y * swp[9] + r2.z * swp[10] + r2.w * swp[11]
              + r3.x * swp[12] + r3.y * swp[13] + r3.z * swp[14] + r3.w * swp[15];
    float sc = dot * inv;
    s[tid] = sc;
    __syncthreads();
    int rank = 0;
    for (int j = 0; j < NPG; j++) {
        float sj = s[j];
        rank += (sj > sc) || (sj == sc && j < tid);
    }
    int kept = rank < KKEEP;
    g_mask[node] = kept ? 1.f : 0.f;
    float fac = kept ? tanhf(sc) : 0.f;
    float4* op = (float4*)(g_hp) + (size_t)node * 4;
    op[0] = make_float4(r0.x * fac, r0.y * fac, r0.z * fac, r0.w * fac);
    op[1] = make_float4(r1.x * fac, r1.y * fac, r1.z * fac, r1.w * fac);
    op[2] = make_float4(r2.x * fac, r2.y * fac, r2.z * fac, r2.w * fac);
    op[3] = make_float4(r3.x * fac, r3.y * fac, r3.z * fac, r3.w * fac);
}

// ---------------- GENConv layer 2 (16 -> 32 -> 32), kept nodes only -------
__global__ __launch_bounds__(256)
void conv2_kernel(const int* __restrict__ eidx,
                  const float* __restrict__ eattr,
                  const float* __restrict__ Wee, const float* __restrict__ bee,
                  const float* __restrict__ tptr,
                  const float* __restrict__ W2a, const float* __restrict__ b2a,
                  const float* __restrict__ g2,  const float* __restrict__ be2,
                  const float* __restrict__ W2b, const float* __restrict__ b2b) {
    __shared__ float sWee[256], sbee[16];
    __shared__ float sW2a[512], sb2a[32], sg2[32], sbe2[32];
    __shared__ float sW2b[1024], sb2b[32];
    __shared__ float sh_hid[8][33];
    int tx = threadIdx.x;
    for (int i = tx; i < 1024; i += 256) sW2b[i] = W2b[i];
    for (int i = tx; i < 512; i += 256) sW2a[i] = W2a[i];
    if (tx < 256) sWee[tx] = Wee[tx];
    if (tx < 32) { sb2a[tx] = b2a[tx]; sg2[tx] = g2[tx]; sbe2[tx] = be2[tx]; sb2b[tx] = b2b[tx]; }
    if (tx < 16) sbee[tx] = bee[tx];
    __syncthreads();

    int w = tx >> 5, lane = tx & 31;
    int node = blockIdx.x * 8 + w;
    if (g_mask[node] == 0.f) return;   // not kept: h2 never read
    int start = g_off[node], end = g_off[node + 1];
    if (start < 0) start = 0;
    if (end > NE) end = NE;
    float t = __ldg(tptr);

    float m[16], den[16], num[16];
    #pragma unroll
    for (int f = 0; f < 16; f++) { m[f] = -INFINITY; den[f] = 0.f; num[f] = 0.f; }

    for (int e0 = start; e0 < end; e0 += 32) {
        int idx = e0 + lane;
        bool act = false;
        float msg[16];
        #pragma unroll
        for (int f = 0; f < 16; f++) msg[f] = 0.f;
        if (idx < end) {
            int eid = __ldg(&g_eids[idx]);
            if ((unsigned)eid >= NE) eid = 0;
            int src = __ldg(&eidx[eid]);
            if ((unsigned)src >= BN) src = 0;
            if (g_mask[src] != 0.f) {
                act = true;
                float at[16], hs[16];
                const float4* ap = (const float4*)(eattr) + (size_t)eid * 4;
                float4 v;
                v = __ldg(ap + 0); at[0] = v.x; at[1] = v.y; at[2] = v.z; at[3] = v.w;
                v = __ldg(ap + 1); at[4] = v.x; at[5] = v.y; at[6] = v.z; at[7] = v.w;
                v = __ldg(ap + 2); at[8] = v.x; at[9] = v.y; at[10] = v.z; at[11] = v.w;
                v = __ldg(ap + 3); at[12] = v.x; at[13] = v.y; at[14] = v.z; at[15] = v.w;
                const float4* hp4 = (const float4*)(g_hp) + (size_t)src * 4;
                v = hp4[0]; hs[0] = v.x; hs[1] = v.y; hs[2] = v.z; hs[3] = v.w;
                v = hp4[1]; hs[4] = v.x; hs[5] = v.y; hs[6] = v.z; hs[7] = v.w;
                v = hp4[2]; hs[8] = v.x; hs[9] = v.y; hs[10] = v.z; hs[11] = v.w;
                v = hp4[3]; hs[12] = v.x; hs[13] = v.y; hs[14] = v.z; hs[15] = v.w;
                #pragma unroll
                for (int f = 0; f < 16; f++) {
                    float acc = sbee[f];
                    #pragma unroll
                    for (int j = 0; j < 16; j++) acc += at[j] * sWee[j * 16 + f];
                    msg[f] = fmaxf(hs[f] + acc, 0.f) + EPSM;
                }
            }
        }
        #pragma unroll
        for (int f = 0; f < 16; f++) {
            float lg = act ? t * msg[f] : -INFINITY;
            float cm = wmax(lg);
            float nm = fmaxf(m[f], cm);
            float ev = act ? __expf(lg - nm) : 0.f;
            float se = wsum(ev);
            float sem = wsum(ev * msg[f]);
            float sc = (nm == -INFINITY) ? 0.f : __expf(m[f] - nm);
            den[f] = den[f] * sc + se;
            num[f] = num[f] * sc + sem;
            m[f] = nm;
        }
    }

    float pre[16];
    #pragma unroll
    for (int f = 0; f < 16; f++)
        pre[f] = g_hp[(size_t)node * 16 + f] + num[f] / fmaxf(den[f], 1e-16f);

    // MLP: 16 -> 32 (LN, relu) -> 32 (then outer relu)
    float acc = sb2a[lane];
    #pragma unroll
    for (int f = 0; f < 16; f++) acc += pre[f] * sW2a[f * 32 + lane];
    float mu = wsum(acc) * (1.f / 32.f);
    float d = acc - mu;
    float var = wsum(d * d) * (1.f / 32.f);
    float y = d * rsqrtf(var + 1e-5f) * sg2[lane] + sbe2[lane];
    y = fmaxf(y, 0.f);
    sh_hid[w][lane] = y;
    __syncwarp();
    float o = sb2b[lane];
    #pragma unroll
    for (int k = 0; k < 32; k++) o += sh_hid[w][k] * sW2b[k * 32 + lane];
    g_h2[(size_t)node * 32 + lane] = fmaxf(o, 0.f);
}

// ---------------- pool + head: out = tanh(relu(pooled@Wa+ba)@Wo+bo) -------
__global__ void final_kernel(const float* __restrict__ Wa, const float* __restrict__ ba,
                             const float* __restrict__ Wo, const float* __restrict__ bo,
                             float* __restrict__ out) {
    __shared__ float part[128];
    __shared__ float pooled[32];
    __shared__ float sa[128];
    int t = threadIdx.x;
    int g = blockIdx.x;
    int c = t & 31, grp = t >> 5;
    float acc = 0.f;
    for (int n = grp; n < NPG; n += 4) {
        int node = g * NPG + n;
        if (g_mask[node] != 0.f) acc += g_h2[(size_t)node * 32 + c];
    }
    part[t] = acc;
    __syncthreads();
    if (t < 32) pooled[t] = (part[t] + part[t + 32] + part[t + 64] + part[t + 96]) * (1.f / KKEEP);
    __syncthreads();
    float a = ba[t];
    #pragma unroll
    for (int cc = 0; cc < 32; cc++) a += pooled[cc] * Wa[cc * 128 + t];
    sa[t] = fmaxf(a, 0.f);
    __syncthreads();
    if (t < 4) {
        float o = bo[t];
        for (int k = 0; k < 128; k++) o += sa[k] * Wo[k * 4 + t];
        out[g * 4 + t] = tanhf(o);
    }
}

// ---------------- launch ----------------
extern "C" void kernel_launch(void* const* d_in, const int* in_sizes, int n_in,
                              void* d_out, int out_size) {
    const float* x    = (const float*)d_in[0];
    const int*   ei   = (const int*)d_in[1];
    const float* ea   = (const float*)d_in[2];
    const float* Wne  = (const float*)d_in[3];
    const float* bne  = (const float*)d_in[4];
    const float* Wee  = (const float*)d_in[5];
    const float* bee  = (const float*)d_in[6];
    const float* t1   = (const float*)d_in[7];
    const float* W1a  = (const float*)d_in[8];
    const float* b1a  = (const float*)d_in[9];
    const float* g1   = (const float*)d_in[10];
    const float* be1  = (const float*)d_in[11];
    const float* W1b  = (const float*)d_in[12];
    const float* b1b  = (const float*)d_in[13];
    const float* wpl  = (const float*)d_in[14];
    const float* t2   = (const float*)d_in[15];
    const float* W2a  = (const float*)d_in[16];
    const float* b2a  = (const float*)d_in[17];
    const float* g2   = (const float*)d_in[18];
    const float* be2  = (const float*)d_in[19];
    const float* W2b  = (const float*)d_in[20];
    const float* b2b  = (const float*)d_in[21];
    const float* Wa   = (const float*)d_in[22];
    const float* ba   = (const float*)d_in[23];
    const float* Wo   = (const float*)d_in[24];
    const float* bo   = (const float*)d_in[25];
    float* out = (float*)d_out;

    zero_counts_kernel<<<BN / 512, 512>>>();
    count_kernel<<<NE / 512, 512>>>(ei);
    scan_kernel<<<1, 1024>>>();
    scatter_kernel<<<NE / 512, 512>>>(ei);
    encode_kernel<<<BN / 256, 256>>>(x, Wne, bne);
    conv1_kernel<<<BN / 8, 256>>>(ei, ea, Wee, bee, t1,
                                  W1a, b1a, g1, be1, W1b, b1b);
    topk_kernel<<<NGRAPH, NPG>>>(wpl);
    conv2_kernel<<<BN / 8, 256>>>(ei, ea, Wee, bee, t2,
                                  W2a, b2a, g2, be2, W2b, b2b);
    final_kernel<<<NGRAPH, 128>>>(Wa, ba, Wo, bo, out);
}

// round 5
// speedup vs baseline: 1.5415x; 1.5415x over previous
#include <cuda_runtime.h>

#define BN      32768      // total nodes
#define NE      1048576    // total edges
#define NPG     512        // nodes per graph
#define KKEEP   256        // topk keep
#define NGRAPH  64
#define EPSM    1e-7f

// ---------------- scratch (device globals; no allocation allowed) ----------
__device__ float g_h   [BN * 16];
__device__ float g_h1  [BN * 16];
__device__ float g_hp  [BN * 16];
__device__ float g_h2  [BN * 32];
__device__ float g_mask[BN];
__device__ int   g_counts[BN];
__device__ int   g_off[BN + 1];
__device__ int   g_cursor[BN];
__device__ int   g_srcs[NE];         // src node id, CSR(dst)-ordered
__device__ float g_ea  [NE * 16];    // encoded edge attr, CSR(dst)-ordered

// ---------------- warp helpers ----------------
__device__ __forceinline__ float wsum(float v) {
    #pragma unroll
    for (int o = 16; o > 0; o >>= 1) v += __shfl_xor_sync(0xffffffffu, v, o);
    return v;
}

// ---------------- CSR build ----------------
__global__ void zero_counts_kernel() {
    int i = blockIdx.x * blockDim.x + threadIdx.x;
    if (i < BN) g_counts[i] = 0;
}

__global__ void count_kernel(const int* __restrict__ ei) {
    int e = blockIdx.x * blockDim.x + threadIdx.x;
    if (e < NE) {
        int d = ei[NE + e];
        if ((unsigned)d < BN) atomicAdd(&g_counts[d], 1);
    }
}

__global__ void scan_kernel() {
    __shared__ int wsums[32];
    __shared__ int carry;
    int tid = threadIdx.x, lane = tid & 31, w = tid >> 5;
    if (tid == 0) { carry = 0; g_off[0] = 0; }
    __syncthreads();
    for (int base = 0; base < BN; base += 1024) {
        int v = g_counts[base + tid];
        int x = v;
        #pragma unroll
        for (int o = 1; o < 32; o <<= 1) {
            int y = __shfl_up_sync(0xffffffffu, x, o);
            if (lane >= o) x += y;
        }
        if (lane == 31) wsums[w] = x;
        __syncthreads();
        if (w == 0) {
            int s = wsums[lane];
            int xs = s;
            #pragma unroll
            for (int o = 1; o < 32; o <<= 1) {
                int y = __shfl_up_sync(0xffffffffu, xs, o);
                if (lane >= o) xs += y;
            }
            wsums[lane] = xs;
        }
        __syncthreads();
        int woff = (w == 0) ? 0 : wsums[w - 1];
        int incl = carry + woff + x;
        g_off[base + tid + 1] = incl;
        g_cursor[base + tid]  = incl - v;
        __syncthreads();
        if (tid == 1023) carry = incl;
        __syncthreads();
    }
}

// scatter + edge-encode fused: coalesced read of eattr, permuted write of enc
__global__ __launch_bounds__(256)
void scatter_encode_kernel(const int* __restrict__ ei,
                           const float* __restrict__ eattr,
                           const float* __restrict__ Wee,
                           const float* __restrict__ bee) {
    __shared__ float sW[256], sb[16];
    int tx = threadIdx.x;
    if (tx < 256) sW[tx] = Wee[tx];
    if (tx < 16) sb[tx] = bee[tx];
    __syncthreads();
    int e = blockIdx.x * blockDim.x + tx;
    if (e >= NE) return;
    int d = ei[NE + e];
    int s = ei[e];
    if ((unsigned)d >= BN) return;
    if ((unsigned)s >= BN) s = 0;

    float at[16];
    const float4* ap = (const float4*)(eattr) + (size_t)e * 4;
    float4 v;
    v = __ldg(ap + 0); at[0] = v.x; at[1] = v.y; at[2]  = v.z; at[3]  = v.w;
    v = __ldg(ap + 1); at[4] = v.x; at[5] = v.y; at[6]  = v.z; at[7]  = v.w;
    v = __ldg(ap + 2); at[8] = v.x; at[9] = v.y; at[10] = v.z; at[11] = v.w;
    v = __ldg(ap + 3); at[12] = v.x; at[13] = v.y; at[14] = v.z; at[15] = v.w;

    float enc[16];
    #pragma unroll
    for (int f = 0; f < 16; f++) {
        float acc = sb[f];
        #pragma unroll
        for (int j = 0; j < 16; j++) acc += at[j] * sW[j * 16 + f];
        enc[f] = acc;
    }

    int p = atomicAdd(&g_cursor[d], 1);
    if ((unsigned)p >= NE) return;
    g_srcs[p] = s;
    float4* op = (float4*)(g_ea) + (size_t)p * 4;
    op[0] = make_float4(enc[0],  enc[1],  enc[2],  enc[3]);
    op[1] = make_float4(enc[4],  enc[5],  enc[6],  enc[7]);
    op[2] = make_float4(enc[8],  enc[9],  enc[10], enc[11]);
    op[3] = make_float4(enc[12], enc[13], enc[14], enc[15]);
}

// ---------------- node encode: h = x @ W_ne + b_ne ----------------
__global__ void encode_kernel(const float* __restrict__ x,
                              const float* __restrict__ Wne,
                              const float* __restrict__ bne) {
    __shared__ float sW[64 * 16];
    __shared__ float sb[16];
    int tx = threadIdx.x;
    for (int i = tx; i < 64 * 16; i += blockDim.x) sW[i] = Wne[i];
    if (tx < 16) sb[tx] = bne[tx];
    __syncthreads();
    int node = blockIdx.x * blockDim.x + tx;
    if (node >= BN) return;
    float acc[16];
    #pragma unroll
    for (int f = 0; f < 16; f++) acc[f] = sb[f];
    const float4* xp = (const float4*)(x + (size_t)node * 64);
    #pragma unroll
    for (int j4 = 0; j4 < 16; j4++) {
        float4 v = __ldg(xp + j4);
        float vv[4] = {v.x, v.y, v.z, v.w};
        #pragma unroll
        for (int k = 0; k < 4; k++) {
            int j = j4 * 4 + k;
            #pragma unroll
            for (int f = 0; f < 16; f++) acc[f] += vv[k] * sW[j * 16 + f];
        }
    }
    float4* op = (float4*)(g_h + (size_t)node * 16);
    op[0] = make_float4(acc[0], acc[1], acc[2], acc[3]);
    op[1] = make_float4(acc[4], acc[5], acc[6], acc[7]);
    op[2] = make_float4(acc[8], acc[9], acc[10], acc[11]);
    op[3] = make_float4(acc[12], acc[13], acc[14], acc[15]);
}

// ---------------- GENConv layer 1 (16 -> 32 -> 16) ----------------
__global__ __launch_bounds__(256)
void conv1_kernel(const float* __restrict__ tptr,
                  const float* __restrict__ W1a, const float* __restrict__ b1a,
                  const float* __restrict__ g1,  const float* __restrict__ be1,
                  const float* __restrict__ W1b, const float* __restrict__ b1b) {
    __shared__ float sW1a[512], sb1a[32], sg1[32], sbe1[32];
    __shared__ float sW1b[512], sb1b[16];
    __shared__ float sh_hid[8][33];
    int tx = threadIdx.x;
    for (int i = tx; i < 512; i += 256) { sW1a[i] = W1a[i]; sW1b[i] = W1b[i]; }
    if (tx < 32) { sb1a[tx] = b1a[tx]; sg1[tx] = g1[tx]; sbe1[tx] = be1[tx]; }
    if (tx < 16) { sb1b[tx] = b1b[tx]; }
    __syncthreads();

    int w = tx >> 5, lane = tx & 31;
    int node = blockIdx.x * 8 + w;
    int start = g_off[node], end = g_off[node + 1];
    if (start < 0) start = 0;
    if (end > NE) end = NE;
    float t = __ldg(tptr);

    float den[16], num[16];
    #pragma unroll
    for (int f = 0; f < 16; f++) { den[f] = 0.f; num[f] = 0.f; }

    for (int e0 = start; e0 < end; e0 += 32) {
        int idx = e0 + lane;
        if (idx < end) {
            int src = g_srcs[idx];
            const float4* ep = (const float4*)(g_ea) + (size_t)idx * 4;
            const float4* hp4 = (const float4*)(g_h) + (size_t)src * 4;
            float4 e0v = ep[0], e1v = ep[1], e2v = ep[2], e3v = ep[3];
            float4 h0 = hp4[0], h1 = hp4[1], h2 = hp4[2], h3 = hp4[3];
            float msg[16];
            msg[0]  = fmaxf(h0.x + e0v.x, 0.f) + EPSM;
            msg[1]  = fmaxf(h0.y + e0v.y, 0.f) + EPSM;
            msg[2]  = fmaxf(h0.z + e0v.z, 0.f) + EPSM;
            msg[3]  = fmaxf(h0.w + e0v.w, 0.f) + EPSM;
            msg[4]  = fmaxf(h1.x + e1v.x, 0.f) + EPSM;
            msg[5]  = fmaxf(h1.y + e1v.y, 0.f) + EPSM;
            msg[6]  = fmaxf(h1.z + e1v.z, 0.f) + EPSM;
            msg[7]  = fmaxf(h1.w + e1v.w, 0.f) + EPSM;
            msg[8]  = fmaxf(h2.x + e2v.x, 0.f) + EPSM;
            msg[9]  = fmaxf(h2.y + e2v.y, 0.f) + EPSM;
            msg[10] = fmaxf(h2.z + e2v.z, 0.f) + EPSM;
            msg[11] = fmaxf(h2.w + e2v.w, 0.f) + EPSM;
            msg[12] = fmaxf(h3.x + e3v.x, 0.f) + EPSM;
            msg[13] = fmaxf(h3.y + e3v.y, 0.f) + EPSM;
            msg[14] = fmaxf(h3.z + e3v.z, 0.f) + EPSM;
            msg[15] = fmaxf(h3.w + e3v.w, 0.f) + EPSM;
            #pragma unroll
            for (int f = 0; f < 16; f++) {
                float ev = __expf(t * msg[f]);
                den[f] += ev;
                num[f] += ev * msg[f];
            }
        }
    }

    // reduce across warp, compute pre = h + num/den
    float pre[16];
    #pragma unroll
    for (int f = 0; f < 16; f++) {
        float dsum = wsum(den[f]);
        float nsum = wsum(num[f]);
        pre[f] = g_h[(size_t)node * 16 + f] + nsum / fmaxf(dsum, 1e-16f);
    }

    // MLP: 16 -> 32 (LN, relu) -> 16 (then outer relu)
    float acc = sb1a[lane];
    #pragma unroll
    for (int f = 0; f < 16; f++) acc += pre[f] * sW1a[f * 32 + lane];
    float mu = wsum(acc) * (1.f / 32.f);
    float d = acc - mu;
    float var = wsum(d * d) * (1.f / 32.f);
    float y = d * rsqrtf(var + 1e-5f) * sg1[lane] + sbe1[lane];
    y = fmaxf(y, 0.f);
    sh_hid[w][lane] = y;
    __syncwarp();
    if (lane < 16) {
        float o = sb1b[lane];
        #pragma unroll
        for (int l = 0; l < 32; l++) o += sh_hid[w][l] * sW1b[l * 16 + lane];
        g_h1[(size_t)node * 16 + lane] = fmaxf(o, 0.f);
    }
}

// ---------------- TopK pooling (score + mask + hp) ----------------
__global__ void topk_kernel(const float* __restrict__ wpool) {
    __shared__ float s[512];
    __shared__ float swp[16];
    int tid = threadIdx.x;
    if (tid < 16) swp[tid] = wpool[tid];
    __syncthreads();
    float nrm2 = 0.f;
    #pragma unroll
    for (int j = 0; j < 16; j++) nrm2 += swp[j] * swp[j];
    float inv = rsqrtf(nrm2);
    int node = blockIdx.x * NPG + tid;
    const float4* hp4 = (const float4*)(g_h1) + (size_t)node * 4;
    float4 r0 = hp4[0], r1 = hp4[1], r2 = hp4[2], r3 = hp4[3];
    float dot = r0.x * swp[0] + r0.y * swp[1] + r0.z * swp[2] + r0.w * swp[3]
              + r1.x * swp[4] + r1.y * swp[5] + r1.z * swp[6] + r1.w * swp[7]
              + r2.x * swp[8] + r2.y * swp[9] + r2.z * swp[10] + r2.w * swp[11]
              + r3.x * swp[12] + r3.y * swp[13] + r3.z * swp[14] + r3.w * swp[15];
    float sc = dot * inv;
    s[tid] = sc;
    __syncthreads();
    int rank = 0;
    for (int j = 0; j < NPG; j++) {
        float sj = s[j];
        rank += (sj > sc) || (sj == sc && j < tid);
    }
    int kept = rank < KKEEP;
    g_mask[node] = kept ? 1.f : 0.f;
    float fac = kept ? tanhf(sc) : 0.f;
    float4* op = (float4*)(g_hp) + (size_t)node * 4;
    op[0] = make_float4(r0.x * fac, r0.y * fac, r0.z * fac, r0.w * fac);
    op[1] = make_float4(r1.x * fac, r1.y * fac, r1.z * fac, r1.w * fac);
    op[2] = make_float4(r2.x * fac, r2.y * fac, r2.z * fac, r2.w * fac);
    op[3] = make_float4(r3.x * fac, r3.y * fac, r3.z * fac, r3.w * fac);
}

// ---------------- GENConv layer 2 (16 -> 32 -> 32), kept nodes only -------
__global__ __launch_bounds__(256)
void conv2_kernel(const float* __restrict__ tptr,
                  const float* __restrict__ W2a, const float* __restrict__ b2a,
                  const float* __restrict__ g2,  const float* __restrict__ be2,
                  const float* __restrict__ W2b, const float* __restrict__ b2b) {
    __shared__ float sW2a[512], sb2a[32], sg2[32], sbe2[32];
    __shared__ float sW2b[1024], sb2b[32];
    __shared__ float sh_hid[8][33];
    int tx = threadIdx.x;
    for (int i = tx; i < 1024; i += 256) sW2b[i] = W2b[i];
    for (int i = tx; i < 512; i += 256) sW2a[i] = W2a[i];
    if (tx < 32) { sb2a[tx] = b2a[tx]; sg2[tx] = g2[tx]; sbe2[tx] = be2[tx]; sb2b[tx] = b2b[tx]; }
    __syncthreads();

    int w = tx >> 5, lane = tx & 31;
    int node = blockIdx.x * 8 + w;
    if (g_mask[node] == 0.f) return;   // not kept: h2 never read
    int start = g_off[node], end = g_off[node + 1];
    if (start < 0) start = 0;
    if (end > NE) end = NE;
    float t = __ldg(tptr);

    float den[16], num[16];
    #pragma unroll
    for (int f = 0; f < 16; f++) { den[f] = 0.f; num[f] = 0.f; }

    for (int e0 = start; e0 < end; e0 += 32) {
        int idx = e0 + lane;
        if (idx < end) {
            int src = g_srcs[idx];
            if (g_mask[src] != 0.f) {
                const float4* ep = (const float4*)(g_ea) + (size_t)idx * 4;
                const float4* hp4 = (const float4*)(g_hp) + (size_t)src * 4;
                float4 e0v = ep[0], e1v = ep[1], e2v = ep[2], e3v = ep[3];
                float4 h0 = hp4[0], h1 = hp4[1], h2 = hp4[2], h3 = hp4[3];
                float msg[16];
                msg[0]  = fmaxf(h0.x + e0v.x, 0.f) + EPSM;
                msg[1]  = fmaxf(h0.y + e0v.y, 0.f) + EPSM;
                msg[2]  = fmaxf(h0.z + e0v.z, 0.f) + EPSM;
                msg[3]  = fmaxf(h0.w + e0v.w, 0.f) + EPSM;
                msg[4]  = fmaxf(h1.x + e1v.x, 0.f) + EPSM;
                msg[5]  = fmaxf(h1.y + e1v.y, 0.f) + EPSM;
                msg[6]  = fmaxf(h1.z + e1v.z, 0.f) + EPSM;
                msg[7]  = fmaxf(h1.w + e1v.w, 0.f) + EPSM;
                msg[8]  = fmaxf(h2.x + e2v.x, 0.f) + EPSM;
                msg[9]  = fmaxf(h2.y + e2v.y, 0.f) + EPSM;
                msg[10] = fmaxf(h2.z + e2v.z, 0.f) + EPSM;
                msg[11] = fmaxf(h2.w + e2v.w, 0.f) + EPSM;
                msg[12] = fmaxf(h3.x + e3v.x, 0.f) + EPSM;
                msg[13] = fmaxf(h3.y + e3v.y, 0.f) + EPSM;
                msg[14] = fmaxf(h3.z + e3v.z, 0.f) + EPSM;
                msg[15] = fmaxf(h3.w + e3v.w, 0.f) + EPSM;
                #pragma unroll
                for (int f = 0; f < 16; f++) {
                    float ev = __expf(t * msg[f]);
                    den[f] += ev;
                    num[f] += ev * msg[f];
                }
            }
        }
    }

    float pre[16];
    #pragma unroll
    for (int f = 0; f < 16; f++) {
        float dsum = wsum(den[f]);
        float nsum = wsum(num[f]);
        pre[f] = g_hp[(size_t)node * 16 + f] + nsum / fmaxf(dsum, 1e-16f);
    }

    // MLP: 16 -> 32 (LN, relu) -> 32 (then outer relu)
    float acc = sb2a[lane];
    #pragma unroll
    for (int f = 0; f < 16; f++) acc += pre[f] * sW2a[f * 32 + lane];
    float mu = wsum(acc) * (1.f / 32.f);
    float d = acc - mu;
    float var = wsum(d * d) * (1.f / 32.f);
    float y = d * rsqrtf(var + 1e-5f) * sg2[lane] + sbe2[lane];
    y = fmaxf(y, 0.f);
    sh_hid[w][lane] = y;
    __syncwarp();
    float o = sb2b[lane];
    #pragma unroll
    for (int k = 0; k < 32; k++) o += sh_hid[w][k] * sW2b[k * 32 + lane];
    g_h2[(size_t)node * 32 + lane] = fmaxf(o, 0.f);
}

// ---------------- pool + head: out = tanh(relu(pooled@Wa+ba)@Wo+bo) -------
__global__ void final_kernel(const float* __restrict__ Wa, const float* __restrict__ ba,
                             const float* __restrict__ Wo, const float* __restrict__ bo,
                             float* __restrict__ out) {
    __shared__ float part[128];
    __shared__ float pooled[32];
    __shared__ float sa[128];
    int t = threadIdx.x;
    int g = blockIdx.x;
    int c = t & 31, grp = t >> 5;
    float acc = 0.f;
    for (int n = grp; n < NPG; n += 4) {
        int node = g * NPG + n;
        if (g_mask[node] != 0.f) acc += g_h2[(size_t)node * 32 + c];
    }
    part[t] = acc;
    __syncthreads();
    if (t < 32) pooled[t] = (part[t] + part[t + 32] + part[t + 64] + part[t + 96]) * (1.f / KKEEP);
    __syncthreads();
    float a = ba[t];
    #pragma unroll
    for (int cc = 0; cc < 32; cc++) a += pooled[cc] * Wa[cc * 128 + t];
    sa[t] = fmaxf(a, 0.f);
    __syncthreads();
    if (t < 4) {
        float o = bo[t];
        for (int k = 0; k < 128; k++) o += sa[k] * Wo[k * 4 + t];
        out[g * 4 + t] = tanhf(o);
    }
}

// ---------------- launch ----------------
extern "C" void kernel_launch(void* const* d_in, const int* in_sizes, int n_in,
                              void* d_out, int out_size) {
    const float* x    = (const float*)d_in[0];
    const int*   ei   = (const int*)d_in[1];
    const float* ea   = (const float*)d_in[2];
    const float* Wne  = (const float*)d_in[3];
    const float* bne  = (const float*)d_in[4];
    const float* Wee  = (const float*)d_in[5];
    const float* bee  = (const float*)d_in[6];
    const float* t1   = (const float*)d_in[7];
    const float* W1a  = (const float*)d_in[8];
    const float* b1a  = (const float*)d_in[9];
    const float* g1   = (const float*)d_in[10];
    const float* be1  = (const float*)d_in[11];
    const float* W1b  = (const float*)d_in[12];
    const float* b1b  = (const float*)d_in[13];
    const float* wpl  = (const float*)d_in[14];
    const float* t2   = (const float*)d_in[15];
    const float* W2a  = (const float*)d_in[16];
    const float* b2a  = (const float*)d_in[17];
    const float* g2   = (const float*)d_in[18];
    const float* be2  = (const float*)d_in[19];
    const float* W2b  = (const float*)d_in[20];
    const float* b2b  = (const float*)d_in[21];
    const float* Wa   = (const float*)d_in[22];
    const float* ba   = (const float*)d_in[23];
    const float* Wo   = (const float*)d_in[24];
    const float* bo   = (const float*)d_in[25];
    float* out = (float*)d_out;

    zero_counts_kernel<<<BN / 512, 512>>>();
    count_kernel<<<NE / 512, 512>>>(ei);
    scan_kernel<<<1, 1024>>>();
    scatter_encode_kernel<<<NE / 256, 256>>>(ei, ea, Wee, bee);
    encode_kernel<<<BN / 256, 256>>>(x, Wne, bne);
    conv1_kernel<<<BN / 8, 256>>>(t1, W1a, b1a, g1, be1, W1b, b1b);
    topk_kernel<<<NGRAPH, NPG>>>(wpl);
    conv2_kernel<<<BN / 8, 256>>>(t2, W2a, b2a, g2, be2, W2b, b2b);
    final_kernel<<<NGRAPH, 128>>>(Wa, ba, Wo, bo, out);
}

// round 7
// speedup vs baseline: 1.6216x; 1.0520x over previous
#include <cuda_runtime.h>

#define BN      32768      // total nodes
#define NE      1048576    // total edges
#define NPG     512        // nodes per graph
#define EPG     16384      // edges per graph
#define KKEEP   256        // topk keep
#define NGRAPH  64
#define EPSM    1e-7f

// ---------------- scratch (device globals; no allocation allowed) ----------
__device__ float g_h   [BN * 16];
__device__ float g_h1  [BN * 16];
__device__ float g_hp  [BN * 16];
__device__ float g_h2  [BN * 32];
__device__ float g_mask[BN];
__device__ int   g_counts[BN];
__device__ int   g_off[BN + 1];
__device__ int   g_cursor[BN];
__device__ int2  g_se  [NE];         // (src, eid) pairs, CSR(dst)-ordered
__device__ float g_ea  [NE * 16];    // encoded edge attr, ORIGINAL edge order

// ---------------- warp helpers ----------------
__device__ __forceinline__ float wsum(float v) {
    #pragma unroll
    for (int o = 16; o > 0; o >>= 1) v += __shfl_xor_sync(0xffffffffu, v, o);
    return v;
}

// ---------------- edge encode (original order, fully coalesced) -----------
__global__ __launch_bounds__(256)
void encode_edges_kernel(const float* __restrict__ eattr,
                         const float* __restrict__ Wee,
                         const float* __restrict__ bee) {
    __shared__ float sW[256], sb[16];
    int tx = threadIdx.x;
    if (tx < 256) sW[tx] = Wee[tx];
    if (tx < 16) sb[tx] = bee[tx];
    __syncthreads();
    int e = blockIdx.x * blockDim.x + tx;
    if (e >= NE) return;

    float at[16];
    const float4* ap = (const float4*)(eattr) + (size_t)e * 4;
    float4 v;
    v = __ldg(ap + 0); at[0] = v.x; at[1] = v.y; at[2]  = v.z; at[3]  = v.w;
    v = __ldg(ap + 1); at[4] = v.x; at[5] = v.y; at[6]  = v.z; at[7]  = v.w;
    v = __ldg(ap + 2); at[8] = v.x; at[9] = v.y; at[10] = v.z; at[11] = v.w;
    v = __ldg(ap + 3); at[12] = v.x; at[13] = v.y; at[14] = v.z; at[15] = v.w;

    float enc[16];
    #pragma unroll
    for (int f = 0; f < 16; f++) {
        float acc = sb[f];
        #pragma unroll
        for (int j = 0; j < 16; j++) acc += at[j] * sW[j * 16 + f];
        enc[f] = acc;
    }
    float4* op = (float4*)(g_ea) + (size_t)e * 4;
    op[0] = make_float4(enc[0],  enc[1],  enc[2],  enc[3]);
    op[1] = make_float4(enc[4],  enc[5],  enc[6],  enc[7]);
    op[2] = make_float4(enc[8],  enc[9],  enc[10], enc[11]);
    op[3] = make_float4(enc[12], enc[13], enc[14], enc[15]);
}

// ---------------- CSR build: per-graph histogram (no global atomics) ------
__global__ __launch_bounds__(512)
void count_hist_kernel(const int* __restrict__ ei) {
    __shared__ int sh[NPG];
    int g = blockIdx.x, tid = threadIdx.x;
    sh[tid] = 0;
    __syncthreads();
    int base = g * EPG;
    #pragma unroll 4
    for (int it = 0; it < EPG / 512; it++) {
        int e = base + it * 512 + tid;
        int d = ei[NE + e] - g * NPG;
        if ((unsigned)d < NPG) atomicAdd(&sh[d], 1);
    }
    __syncthreads();
    g_counts[g * NPG + tid] = sh[tid];
}

// per-graph parallel exclusive scan (base = g*EPG)
__global__ __launch_bounds__(512)
void scan_graph_kernel() {
    __shared__ int wsums[16];
    int g = blockIdx.x, tid = threadIdx.x, lane = tid & 31, w = tid >> 5;
    int node = g * NPG + tid;
    int v = g_counts[node];
    int x = v;
    #pragma unroll
    for (int o = 1; o < 32; o <<= 1) {
        int y = __shfl_up_sync(0xffffffffu, x, o);
        if (lane >= o) x += y;
    }
    if (lane == 31) wsums[w] = x;
    __syncthreads();
    if (w == 0) {
        int s = (lane < 16) ? wsums[lane] : 0;
        #pragma unroll
        for (int o = 1; o < 16; o <<= 1) {
            int y = __shfl_up_sync(0xffffffffu, s, o);
            if (lane >= o) s += y;
        }
        if (lane < 16) wsums[lane] = s;
    }
    __syncthreads();
    int woff = (w == 0) ? 0 : wsums[w - 1];
    int incl = woff + x;
    g_off[node + 1]  = g * EPG + incl;
    g_cursor[node]   = g * EPG + incl - v;
    if (g == 0 && tid == 0) g_off[0] = 0;
}

// scatter (src, eid) pairs into CSR(dst) order — 8B per edge
__global__ __launch_bounds__(512)
void scatter_kernel(const int* __restrict__ ei) {
    int e = blockIdx.x * blockDim.x + threadIdx.x;
    if (e < NE) {
        int d = ei[NE + e];
        int s = ei[e];
        if ((unsigned)d >= BN) return;
        if ((unsigned)s >= BN) s = 0;
        int p = atomicAdd(&g_cursor[d], 1);
        if ((unsigned)p < NE) g_se[p] = make_int2(s, e);
    }
}

// ---------------- node encode: h = x @ W_ne + b_ne ----------------
__global__ void encode_kernel(const float* __restrict__ x,
                              const float* __restrict__ Wne,
                              const float* __restrict__ bne) {
    __shared__ float sW[64 * 16];
    __shared__ float sb[16];
    int tx = threadIdx.x;
    for (int i = tx; i < 64 * 16; i += blockDim.x) sW[i] = Wne[i];
    if (tx < 16) sb[tx] = bne[tx];
    __syncthreads();
    int node = blockIdx.x * blockDim.x + tx;
    if (node >= BN) return;
    float acc[16];
    #pragma unroll
    for (int f = 0; f < 16; f++) acc[f] = sb[f];
    const float4* xp = (const float4*)(x + (size_t)node * 64);
    #pragma unroll
    for (int j4 = 0; j4 < 16; j4++) {
        float4 v = __ldg(xp + j4);
        float vv[4] = {v.x, v.y, v.z, v.w};
        #pragma unroll
        for (int k = 0; k < 4; k++) {
            int j = j4 * 4 + k;
            #pragma unroll
            for (int f = 0; f < 16; f++) acc[f] += vv[k] * sW[j * 16 + f];
        }
    }
    float4* op = (float4*)(g_h + (size_t)node * 16);
    op[0] = make_float4(acc[0], acc[1], acc[2], acc[3]);
    op[1] = make_float4(acc[4], acc[5], acc[6], acc[7]);
    op[2] = make_float4(acc[8], acc[9], acc[10], acc[11]);
    op[3] = make_float4(acc[12], acc[13], acc[14], acc[15]);
}

// ---------------- GENConv layer 1 (16 -> 32 -> 16) ----------------
__global__ __launch_bounds__(256)
void conv1_kernel(const float* __restrict__ tptr,
                  const float* __restrict__ W1a, const float* __restrict__ b1a,
                  const float* __restrict__ g1,  const float* __restrict__ be1,
                  const float* __restrict__ W1b, const float* __restrict__ b1b) {
    __shared__ float sW1a[512], sb1a[32], sg1[32], sbe1[32];
    __shared__ float sW1b[512], sb1b[16];
    __shared__ float sh_hid[8][33];
    int tx = threadIdx.x;
    for (int i = tx; i < 512; i += 256) { sW1a[i] = W1a[i]; sW1b[i] = W1b[i]; }
    if (tx < 32) { sb1a[tx] = b1a[tx]; sg1[tx] = g1[tx]; sbe1[tx] = be1[tx]; }
    if (tx < 16) { sb1b[tx] = b1b[tx]; }
    __syncthreads();

    int w = tx >> 5, lane = tx & 31;
    int node = blockIdx.x * 8 + w;
    int start = g_off[node], end = g_off[node + 1];
    if (start < 0) start = 0;
    if (end > NE) end = NE;
    float t = __ldg(tptr);

    float den[16], num[16];
    #pragma unroll
    for (int f = 0; f < 16; f++) { den[f] = 0.f; num[f] = 0.f; }

    for (int e0 = start; e0 < end; e0 += 32) {
        int idx = e0 + lane;
        if (idx < end) {
            int2 se = g_se[idx];
            int src = se.x, eid = se.y;
            const float4* ep  = (const float4*)(g_ea) + (size_t)eid * 4;
            const float4* hp4 = (const float4*)(g_h)  + (size_t)src * 4;
            float4 e0v = ep[0], e1v = ep[1], e2v = ep[2], e3v = ep[3];
            float4 h0 = hp4[0], h1 = hp4[1], h2 = hp4[2], h3 = hp4[3];
            float msg[16];
            msg[0]  = fmaxf(h0.x + e0v.x, 0.f) + EPSM;
            msg[1]  = fmaxf(h0.y + e0v.y, 0.f) + EPSM;
            msg[2]  = fmaxf(h0.z + e0v.z, 0.f) + EPSM;
            msg[3]  = fmaxf(h0.w + e0v.w, 0.f) + EPSM;
            msg[4]  = fmaxf(h1.x + e1v.x, 0.f) + EPSM;
            msg[5]  = fmaxf(h1.y + e1v.y, 0.f) + EPSM;
            msg[6]  = fmaxf(h1.z + e1v.z, 0.f) + EPSM;
            msg[7]  = fmaxf(h1.w + e1v.w, 0.f) + EPSM;
            msg[8]  = fmaxf(h2.x + e2v.x, 0.f) + EPSM;
            msg[9]  = fmaxf(h2.y + e2v.y, 0.f) + EPSM;
            msg[10] = fmaxf(h2.z + e2v.z, 0.f) + EPSM;
            msg[11] = fmaxf(h2.w + e2v.w, 0.f) + EPSM;
            msg[12] = fmaxf(h3.x + e3v.x, 0.f) + EPSM;
            msg[13] = fmaxf(h3.y + e3v.y, 0.f) + EPSM;
            msg[14] = fmaxf(h3.z + e3v.z, 0.f) + EPSM;
            msg[15] = fmaxf(h3.w + e3v.w, 0.f) + EPSM;
            #pragma unroll
            for (int f = 0; f < 16; f++) {
                float ev = __expf(t * msg[f]);
                den[f] += ev;
                num[f] += ev * msg[f];
            }
        }
    }

    float pre[16];
    #pragma unroll
    for (int f = 0; f < 16; f++) {
        float dsum = wsum(den[f]);
        float nsum = wsum(num[f]);
        pre[f] = g_h[(size_t)node * 16 + f] + nsum / fmaxf(dsum, 1e-16f);
    }

    // MLP: 16 -> 32 (LN, relu) -> 16 (then outer relu)
    float acc = sb1a[lane];
    #pragma unroll
    for (int f = 0; f < 16; f++) acc += pre[f] * sW1a[f * 32 + lane];
    float mu = wsum(acc) * (1.f / 32.f);
    float d = acc - mu;
    float var = wsum(d * d) * (1.f / 32.f);
    float y = d * rsqrtf(var + 1e-5f) * sg1[lane] + sbe1[lane];
    y = fmaxf(y, 0.f);
    sh_hid[w][lane] = y;
    __syncwarp();
    if (lane < 16) {
        float o = sb1b[lane];
        #pragma unroll
        for (int l = 0; l < 32; l++) o += sh_hid[w][l] * sW1b[l * 16 + lane];
        g_h1[(size_t)node * 16 + lane] = fmaxf(o, 0.f);
    }
}

// ---------------- TopK pooling (score + mask + hp) ----------------
__global__ void topk_kernel(const float* __restrict__ wpool) {
    __shared__ float s[512];
    __shared__ float swp[16];
    int tid = threadIdx.x;
    if (tid < 16) swp[tid] = wpool[tid];
    __syncthreads();
    float nrm2 = 0.f;
    #pragma unroll
    for (int j = 0; j < 16; j++) nrm2 += swp[j] * swp[j];
    float inv = rsqrtf(nrm2);
    int node = blockIdx.x * NPG + tid;
    const float4* hp4 = (const float4*)(g_h1) + (size_t)node * 4;
    float4 r0 = hp4[0], r1 = hp4[1], r2 = hp4[2], r3 = hp4[3];
    float dot = r0.x * swp[0] + r0.y * swp[1] + r0.z * swp[2] + r0.w * swp[3]
              + r1.x * swp[4] + r1.y * swp[5] + r1.z * swp[6] + r1.w * swp[7]
              + r2.x * swp[8] + r2.y * swp[9] + r2.z * swp[10] + r2.w * swp[11]
              + r3.x * swp[12] + r3.y * swp[13] + r3.z * swp[14] + r3.w * swp[15];
    float sc = dot * inv;
    s[tid] = sc;
    __syncthreads();
    int rank = 0;
    for (int j = 0; j < NPG; j++) {
        float sj = s[j];
        rank += (sj > sc) || (sj == sc && j < tid);
    }
    int kept = rank < KKEEP;
    g_mask[node] = kept ? 1.f : 0.f;
    float fac = kept ? tanhf(sc) : 0.f;
    float4* op = (float4*)(g_hp) + (size_t)node * 4;
    op[0] = make_float4(r0.x * fac, r0.y * fac, r0.z * fac, r0.w * fac);
    op[1] = make_float4(r1.x * fac, r1.y * fac, r1.z * fac, r1.w * fac);
    op[2] = make_float4(r2.x * fac, r2.y * fac, r2.z * fac, r2.w * fac);
    op[3] = make_float4(r3.x * fac, r3.y * fac, r3.z * fac, r3.w * fac);
}

// ---------------- GENConv layer 2 (16 -> 32 -> 32), kept nodes only -------
__global__ __launch_bounds__(256)
void conv2_kernel(const float* __restrict__ tptr,
                  const float* __restrict__ W2a, const float* __restrict__ b2a,
                  const float* __restrict__ g2,  const float* __restrict__ be2,
                  const float* __restrict__ W2b, const float* __restrict__ b2b) {
    __shared__ float sW2a[512], sb2a[32], sg2[32], sbe2[32];
    __shared__ float sW2b[1024], sb2b[32];
    __shared__ float sh_hid[8][33];
    int tx = threadIdx.x;
    for (int i = tx; i < 1024; i += 256) sW2b[i] = W2b[i];
    for (int i = tx; i < 512; i += 256) sW2a[i] = W2a[i];
    if (tx < 32) { sb2a[tx] = b2a[tx]; sg2[tx] = g2[tx]; sbe2[tx] = be2[tx]; sb2b[tx] = b2b[tx]; }
    __syncthreads();

    int w = tx >> 5, lane = tx & 31;
    int node = blockIdx.x * 8 + w;
    if (g_mask[node] == 0.f) return;   // not kept: h2 never read
    int start = g_off[node], end = g_off[node + 1];
    if (start < 0) start = 0;
    if (end > NE) end = NE;
    float t = __ldg(tptr);

    float den[16], num[16];
    #pragma unroll
    for (int f = 0; f < 16; f++) { den[f] = 0.f; num[f] = 0.f; }

    for (int e0 = start; e0 < end; e0 += 32) {
        int idx = e0 + lane;
        if (idx < end) {
            int2 se = g_se[idx];
            int src = se.x, eid = se.y;
            if (g_mask[src] != 0.f) {
                const float4* ep  = (const float4*)(g_ea) + (size_t)eid * 4;
                const float4* hp4 = (const float4*)(g_hp) + (size_t)src * 4;
                float4 e0v = ep[0], e1v = ep[1], e2v = ep[2], e3v = ep[3];
                float4 h0 = hp4[0], h1 = hp4[1], h2 = hp4[2], h3 = hp4[3];
                float msg[16];
                msg[0]  = fmaxf(h0.x + e0v.x, 0.f) + EPSM;
                msg[1]  = fmaxf(h0.y + e0v.y, 0.f) + EPSM;
                msg[2]  = fmaxf(h0.z + e0v.z, 0.f) + EPSM;
                msg[3]  = fmaxf(h0.w + e0v.w, 0.f) + EPSM;
                msg[4]  = fmaxf(h1.x + e1v.x, 0.f) + EPSM;
                msg[5]  = fmaxf(h1.y + e1v.y, 0.f) + EPSM;
                msg[6]  = fmaxf(h1.z + e1v.z, 0.f) + EPSM;
                msg[7]  = fmaxf(h1.w + e1v.w, 0.f) + EPSM;
                msg[8]  = fmaxf(h2.x + e2v.x, 0.f) + EPSM;
                msg[9]  = fmaxf(h2.y + e2v.y, 0.f) + EPSM;
                msg[10] = fmaxf(h2.z + e2v.z, 0.f) + EPSM;
                msg[11] = fmaxf(h2.w + e2v.w, 0.f) + EPSM;
                msg[12] = fmaxf(h3.x + e3v.x, 0.f) + EPSM;
                msg[13] = fmaxf(h3.y + e3v.y, 0.f) + EPSM;
                msg[14] = fmaxf(h3.z + e3v.z, 0.f) + EPSM;
                msg[15] = fmaxf(h3.w + e3v.w, 0.f) + EPSM;
                #pragma unroll
                for (int f = 0; f < 16; f++) {
                    float ev = __expf(t * msg[f]);
                    den[f] += ev;
                    num[f] += ev * msg[f];
                }
            }
        }
    }

    float pre[16];
    #pragma unroll
    for (int f = 0; f < 16; f++) {
        float dsum = wsum(den[f]);
        float nsum = wsum(num[f]);
        pre[f] = g_hp[(size_t)node * 16 + f] + nsum / fmaxf(dsum, 1e-16f);
    }

    // MLP: 16 -> 32 (LN, relu) -> 32 (then outer relu)
    float acc = sb2a[lane];
    #pragma unroll
    for (int f = 0; f < 16; f++) acc += pre[f] * sW2a[f * 32 + lane];
    float mu = wsum(acc) * (1.f / 32.f);
    float d = acc - mu;
    float var = wsum(d * d) * (1.f / 32.f);
    float y = d * rsqrtf(var + 1e-5f) * sg2[lane] + sbe2[lane];
    y = fmaxf(y, 0.f);
    sh_hid[w][lane] = y;
    __syncwarp();
    float o = sb2b[lane];
    #pragma unroll
    for (int k = 0; k < 32; k++) o += sh_hid[w][k] * sW2b[k * 32 + lane];
    g_h2[(size_t)node * 32 + lane] = fmaxf(o, 0.f);
}

// ---------------- pool + head: out = tanh(relu(pooled@Wa+ba)@Wo+bo) -------
__global__ void final_kernel(const float* __restrict__ Wa, const float* __restrict__ ba,
                             const float* __restrict__ Wo, const float* __restrict__ bo,
                             float* __restrict__ out) {
    __shared__ float part[128];
    __shared__ float pooled[32];
    __shared__ float sa[128];
    int t = threadIdx.x;
    int g = blockIdx.x;
    int c = t & 31, grp = t >> 5;
    float acc = 0.f;
    for (int n = grp; n < NPG; n += 4) {
        int node = g * NPG + n;
        if (g_mask[node] != 0.f) acc += g_h2[(size_t)node * 32 + c];
    }
    part[t] = acc;
    __syncthreads();
    if (t < 32) pooled[t] = (part[t] + part[t + 32] + part[t + 64] + part[t + 96]) * (1.f / KKEEP);
    __syncthreads();
    float a = ba[t];
    #pragma unroll
    for (int cc = 0; cc < 32; cc++) a += pooled[cc] * Wa[cc * 128 + t];
    sa[t] = fmaxf(a, 0.f);
    __syncthreads();
    if (t < 4) {
        float o = bo[t];
        for (int k = 0; k < 128; k++) o += sa[k] * Wo[k * 4 + t];
        out[g * 4 + t] = tanhf(o);
    }
}

// ---------------- launch ----------------
extern "C" void kernel_launch(void* const* d_in, const int* in_sizes, int n_in,
                              void* d_out, int out_size) {
    const float* x    = (const float*)d_in[0];
    const int*   ei   = (const int*)d_in[1];
    const float* ea   = (const float*)d_in[2];
    const float* Wne  = (const float*)d_in[3];
    const float* bne  = (const float*)d_in[4];
    const float* Wee  = (const float*)d_in[5];
    const float* bee  = (const float*)d_in[6];
    const float* t1   = (const float*)d_in[7];
    const float* W1a  = (const float*)d_in[8];
    const float* b1a  = (const float*)d_in[9];
    const float* g1   = (const float*)d_in[10];
    const float* be1  = (const float*)d_in[11];
    const float* W1b  = (const float*)d_in[12];
    const float* b1b  = (const float*)d_in[13];
    const float* wpl  = (const float*)d_in[14];
    const float* t2   = (const float*)d_in[15];
    const float* W2a  = (const float*)d_in[16];
    const float* b2a  = (const float*)d_in[17];
    const float* g2   = (const float*)d_in[18];
    const float* be2  = (const float*)d_in[19];
    const float* W2b  = (const float*)d_in[20];
    const float* b2b  = (const float*)d_in[21];
    const float* Wa   = (const float*)d_in[22];
    const float* ba   = (const float*)d_in[23];
    const float* Wo   = (const float*)d_in[24];
    const float* bo   = (const float*)d_in[25];
    float* out = (float*)d_out;

    count_hist_kernel<<<NGRAPH, 512>>>(ei);
    encode_edges_kernel<<<NE / 256, 256>>>(ea, Wee, bee);
    scan_graph_kernel<<<NGRAPH, 512>>>();
    scatter_kernel<<<NE / 512, 512>>>(ei);
    encode_kernel<<<BN / 256, 256>>>(x, Wne, bne);
    conv1_kernel<<<BN / 8, 256>>>(t1, W1a, b1a, g1, be1, W1b, b1b);
    topk_kernel<<<NGRAPH, NPG>>>(wpl);
    conv2_kernel<<<BN / 8, 256>>>(t2, W2a, b2a, g2, be2, W2b, b2b);
    final_kernel<<<NGRAPH, 128>>>(Wa, ba, Wo, bo, out);
}